// round 6
// baseline (speedup 1.0000x reference)
#include <cuda_runtime.h>
#include <cstdint>

// EmbeddingDropout: out[r, :] = weight[x[r], :] * rowmask(x[r])
// rowmask: bit-exact jax.random.bernoulli(jax.random.key(42), 0.9, (50257,1))
// under the partitionable threefry path (JAX >= 0.4.30 default):
//   (o0,o1) = threefry2x32(key=(0,42), (hi32(v)=0, lo32(v)=v)); bits = o0^o1
//   u = bitcast((bits>>9)|0x3f800000) - 1.0f;  keep = u < 0.9f; scale = keep/0.9
// x indices arrive as int32 (JAX x64-disabled demotes jnp.int64 -> int32).

#define TF_ROUND(r) { x0 += x1; x1 = (x1 << (r)) | (x1 >> (32 - (r))); x1 ^= x0; }

__device__ __forceinline__ float row_scale(uint32_t v)
{
    const uint32_t k0 = 0u;
    const uint32_t k1 = 42u;
    const uint32_t k2 = 0u ^ 42u ^ 0x1BD11BDAu;

    uint32_t x0 = 0u;   // hi32 of uint64 counter
    uint32_t x1 = v;    // lo32

    x0 += k0; x1 += k1;
    TF_ROUND(13) TF_ROUND(15) TF_ROUND(26) TF_ROUND(6)
    x0 += k1; x1 += k2 + 1u;
    TF_ROUND(17) TF_ROUND(29) TF_ROUND(16) TF_ROUND(24)
    x0 += k2; x1 += k0 + 2u;
    TF_ROUND(13) TF_ROUND(15) TF_ROUND(26) TF_ROUND(6)
    x0 += k0; x1 += k1 + 3u;
    TF_ROUND(17) TF_ROUND(29) TF_ROUND(16) TF_ROUND(24)
    x0 += k1; x1 += k2 + 4u;
    TF_ROUND(13) TF_ROUND(15) TF_ROUND(26) TF_ROUND(6)
    x0 += k2; x1 += k0 + 5u;

    uint32_t bits = x0 ^ x1;

    float u = __uint_as_float((bits >> 9) | 0x3f800000u) - 1.0f;
    return (u < 0.9f) ? (1.0f / 0.9f) : 0.0f;
}

// One warp per row: 32 lanes x 8 float4 = 1024 floats. 8 rows per CTA.
// 8 independent LDG.128s per thread batched before any store -> MLP=8,
// roughly 2x the in-flight bytes of the previous 4-float4 version.
__global__ void __launch_bounds__(256)
embedding_dropout_kernel(const int* __restrict__ x,
                         const float* __restrict__ weight,
                         float* __restrict__ out)
{
    const int warp = threadIdx.x >> 5;         // 0..7: row within CTA
    const int lane = threadIdx.x & 31;
    const int row  = (blockIdx.x << 3) + warp;

    int idx = x[row];
    idx = (idx < 0) ? 0 : ((idx > 50256) ? 50256 : idx);

    const float s = row_scale((uint32_t)idx);  // warp-uniform

    const float4* __restrict__ src =
        reinterpret_cast<const float4*>(weight + (long long)idx * 1024ll) + lane;
    float4* __restrict__ dst =
        reinterpret_cast<float4*>(out + (long long)row * 1024ll) + lane;

    float4 v[8];
#pragma unroll
    for (int i = 0; i < 8; i++)
        v[i] = __ldg(src + 32 * i);            // 8 loads in flight

#pragma unroll
    for (int i = 0; i < 8; i++) {
        v[i].x *= s; v[i].y *= s; v[i].z *= s; v[i].w *= s;
        dst[32 * i] = v[i];
    }
}

extern "C" void kernel_launch(void* const* d_in, const int* in_sizes, int n_in,
                              void* d_out, int out_size)
{
    // Robust to input ordering: x has 16,384 elements, weight has 51,463,168.
    int xi = 0, wi = 1;
    if (n_in >= 2 && in_sizes[0] > in_sizes[1]) { xi = 1; wi = 0; }

    const int* x = (const int*)d_in[xi];          // int32 [8,2048]
    const float* weight = (const float*)d_in[wi]; // f32 [50257,1024]
    float* out = (float*)d_out;                   // f32 [8,2048,1024]

    const int n_rows = in_sizes[xi];              // 16384 (divisible by 8)
    embedding_dropout_kernel<<<n_rows / 8, 256>>>(x, weight, out);
}

// round 9
// speedup vs baseline: 1.1268x; 1.1268x over previous
#include <cuda_runtime.h>
#include <cstdint>

// EmbeddingDropout: out[r, :] = weight[x[r], :] * rowmask(x[r])
// rowmask: bit-exact jax.random.bernoulli(jax.random.key(42), 0.9, (50257,1))
// under the partitionable threefry path (JAX >= 0.4.30 default):
//   (o0,o1) = threefry2x32(key=(0,42), (hi32(v)=0, lo32(v)=v)); bits = o0^o1
//   u = bitcast((bits>>9)|0x3f800000) - 1.0f;  keep = u < 0.9f; scale = keep/0.9
// x indices arrive as int32 (JAX x64-disabled demotes jnp.int64 -> int32).

#define TF_ROUND(r) { x0 += x1; x1 = (x1 << (r)) | (x1 >> (32 - (r))); x1 ^= x0; }

__device__ __forceinline__ float row_scale(uint32_t v)
{
    const uint32_t k0 = 0u;
    const uint32_t k1 = 42u;
    const uint32_t k2 = 0u ^ 42u ^ 0x1BD11BDAu;

    uint32_t x0 = 0u;   // hi32 of uint64 counter
    uint32_t x1 = v;    // lo32

    x0 += k0; x1 += k1;
    TF_ROUND(13) TF_ROUND(15) TF_ROUND(26) TF_ROUND(6)
    x0 += k1; x1 += k2 + 1u;
    TF_ROUND(17) TF_ROUND(29) TF_ROUND(16) TF_ROUND(24)
    x0 += k2; x1 += k0 + 2u;
    TF_ROUND(13) TF_ROUND(15) TF_ROUND(26) TF_ROUND(6)
    x0 += k0; x1 += k1 + 3u;
    TF_ROUND(17) TF_ROUND(29) TF_ROUND(16) TF_ROUND(24)
    x0 += k1; x1 += k2 + 4u;
    TF_ROUND(13) TF_ROUND(15) TF_ROUND(26) TF_ROUND(6)
    x0 += k2; x1 += k0 + 5u;

    uint32_t bits = x0 ^ x1;

    float u = __uint_as_float((bits >> 9) | 0x3f800000u) - 1.0f;
    return (u < 0.9f) ? (1.0f / 0.9f) : 0.0f;
}

// 4 rows per CTA (256 threads): 64 threads per row, 4 explicitly-named float4s
// per thread (genuine MLP=4 in SASS at ~26 regs). min-blocks=8 -> 64 warps/SM
// residency (R4 was capped at 48 by min-blocks=6).
__global__ void __launch_bounds__(256, 8)
embedding_dropout_kernel(const int* __restrict__ x,
                         const float* __restrict__ weight,
                         float* __restrict__ out)
{
    const int sub = threadIdx.x >> 6;          // 0..3: which row in this CTA
    const int t   = threadIdx.x & 63;          // 0..63: lane within row
    const int row = (blockIdx.x << 2) + sub;

    int idx = x[row];
    idx = (idx < 0) ? 0 : ((idx > 50256) ? 50256 : idx);

    const float s = row_scale((uint32_t)idx);

    const float4* __restrict__ src =
        reinterpret_cast<const float4*>(weight + (long long)idx * 1024ll) + t;
    float4* __restrict__ dst =
        reinterpret_cast<float4*>(out + (long long)row * 1024ll) + t;

    // 4 independent loads in flight before any store (named regs, not an array,
    // so ptxas keeps them live and batched).
    float4 v0 = __ldg(src);
    float4 v1 = __ldg(src + 64);
    float4 v2 = __ldg(src + 128);
    float4 v3 = __ldg(src + 192);

    v0.x *= s; v0.y *= s; v0.z *= s; v0.w *= s;
    v1.x *= s; v1.y *= s; v1.z *= s; v1.w *= s;
    v2.x *= s; v2.y *= s; v2.z *= s; v2.w *= s;
    v3.x *= s; v3.y *= s; v3.z *= s; v3.w *= s;

    dst[0]   = v0;
    dst[64]  = v1;
    dst[128] = v2;
    dst[192] = v3;
}

extern "C" void kernel_launch(void* const* d_in, const int* in_sizes, int n_in,
                              void* d_out, int out_size)
{
    // Robust to input ordering: x has 16,384 elements, weight has 51,463,168.
    int xi = 0, wi = 1;
    if (n_in >= 2 && in_sizes[0] > in_sizes[1]) { xi = 1; wi = 0; }

    const int* x = (const int*)d_in[xi];          // int32 [8,2048]
    const float* weight = (const float*)d_in[wi]; // f32 [50257,1024]
    float* out = (float*)d_out;                   // f32 [8,2048,1024]

    const int n_rows = in_sizes[xi];              // 16384 (divisible by 4)
    embedding_dropout_kernel<<<n_rows / 4, 256>>>(x, weight, out);
}

// round 10
// speedup vs baseline: 1.2076x; 1.0718x over previous
#include <cuda_runtime.h>
#include <cstdint>

// EmbeddingDropout: out[r, :] = weight[x[r], :] * rowmask(x[r])
// rowmask: bit-exact jax.random.bernoulli(jax.random.key(42), 0.9, (50257,1))
// under the partitionable threefry path (JAX >= 0.4.30 default):
//   (o0,o1) = threefry2x32(key=(0,42), (hi32(v)=0, lo32(v)=v)); bits = o0^o1
//   u = bitcast((bits>>9)|0x3f800000) - 1.0f;  keep = u < 0.9f; scale = keep/0.9
// x indices arrive as int32 (JAX x64-disabled demotes jnp.int64 -> int32).

#define TF_ROUND(r) { x0 += x1; x1 = (x1 << (r)) | (x1 >> (32 - (r))); x1 ^= x0; }

__device__ __forceinline__ float row_scale(uint32_t v)
{
    const uint32_t k0 = 0u;
    const uint32_t k1 = 42u;
    const uint32_t k2 = 0u ^ 42u ^ 0x1BD11BDAu;

    uint32_t x0 = 0u;   // hi32 of uint64 counter
    uint32_t x1 = v;    // lo32

    x0 += k0; x1 += k1;
    TF_ROUND(13) TF_ROUND(15) TF_ROUND(26) TF_ROUND(6)
    x0 += k1; x1 += k2 + 1u;
    TF_ROUND(17) TF_ROUND(29) TF_ROUND(16) TF_ROUND(24)
    x0 += k2; x1 += k0 + 2u;
    TF_ROUND(13) TF_ROUND(15) TF_ROUND(26) TF_ROUND(6)
    x0 += k0; x1 += k1 + 3u;
    TF_ROUND(17) TF_ROUND(29) TF_ROUND(16) TF_ROUND(24)
    x0 += k1; x1 += k2 + 4u;
    TF_ROUND(13) TF_ROUND(15) TF_ROUND(26) TF_ROUND(6)
    x0 += k2; x1 += k0 + 5u;

    uint32_t bits = x0 ^ x1;

    float u = __uint_as_float((bits >> 9) | 0x3f800000u) - 1.0f;
    return (u < 0.9f) ? (1.0f / 0.9f) : 0.0f;
}

// 8 rows per CTA (256 threads): each 64-thread group handles TWO rows,
// 4 named float4s from each -> 8 independent LDG.128s in flight per thread
// before any store. Named scalars (not arrays) so ptxas must keep all 8
// loads co-live (data alone = 32 regs). No min-blocks cap: let ptxas pick.
__global__ void __launch_bounds__(256)
embedding_dropout_kernel(const int* __restrict__ x,
                         const float* __restrict__ weight,
                         float* __restrict__ out)
{
    const int g = threadIdx.x >> 6;            // 0..3: group within CTA
    const int t = threadIdx.x & 63;            // 0..63: lane within group
    const int rowA = (blockIdx.x << 3) + (g << 1);
    const int rowB = rowA + 1;

    int idxA = x[rowA];
    int idxB = x[rowB];
    idxA = (idxA < 0) ? 0 : ((idxA > 50256) ? 50256 : idxA);
    idxB = (idxB < 0) ? 0 : ((idxB > 50256) ? 50256 : idxB);

    const float sA = row_scale((uint32_t)idxA);
    const float sB = row_scale((uint32_t)idxB);

    const float4* __restrict__ srcA =
        reinterpret_cast<const float4*>(weight + (long long)idxA * 1024ll) + t;
    const float4* __restrict__ srcB =
        reinterpret_cast<const float4*>(weight + (long long)idxB * 1024ll) + t;
    float4* __restrict__ dstA =
        reinterpret_cast<float4*>(out + (long long)rowA * 1024ll) + t;
    float4* __restrict__ dstB =
        reinterpret_cast<float4*>(out + (long long)rowB * 1024ll) + t;

    // 8 independent loads in flight before any store.
    float4 a0 = __ldg(srcA);
    float4 a1 = __ldg(srcA + 64);
    float4 a2 = __ldg(srcA + 128);
    float4 a3 = __ldg(srcA + 192);
    float4 b0 = __ldg(srcB);
    float4 b1 = __ldg(srcB + 64);
    float4 b2 = __ldg(srcB + 128);
    float4 b3 = __ldg(srcB + 192);

    a0.x *= sA; a0.y *= sA; a0.z *= sA; a0.w *= sA;
    a1.x *= sA; a1.y *= sA; a1.z *= sA; a1.w *= sA;
    a2.x *= sA; a2.y *= sA; a2.z *= sA; a2.w *= sA;
    a3.x *= sA; a3.y *= sA; a3.z *= sA; a3.w *= sA;
    b0.x *= sB; b0.y *= sB; b0.z *= sB; b0.w *= sB;
    b1.x *= sB; b1.y *= sB; b1.z *= sB; b1.w *= sB;
    b2.x *= sB; b2.y *= sB; b2.z *= sB; b2.w *= sB;
    b3.x *= sB; b3.y *= sB; b3.z *= sB; b3.w *= sB;

    dstA[0]   = a0;
    dstA[64]  = a1;
    dstA[128] = a2;
    dstA[192] = a3;
    dstB[0]   = b0;
    dstB[64]  = b1;
    dstB[128] = b2;
    dstB[192] = b3;
}

extern "C" void kernel_launch(void* const* d_in, const int* in_sizes, int n_in,
                              void* d_out, int out_size)
{
    // Robust to input ordering: x has 16,384 elements, weight has 51,463,168.
    int xi = 0, wi = 1;
    if (n_in >= 2 && in_sizes[0] > in_sizes[1]) { xi = 1; wi = 0; }

    const int* x = (const int*)d_in[xi];          // int32 [8,2048]
    const float* weight = (const float*)d_in[wi]; // f32 [50257,1024]
    float* out = (float*)d_out;                   // f32 [8,2048,1024]

    const int n_rows = in_sizes[xi];              // 16384 (divisible by 8)
    embedding_dropout_kernel<<<n_rows / 8, 256>>>(x, weight, out);
}